// round 8
// baseline (speedup 1.0000x reference)
#include <cuda_runtime.h>
#include <math.h>
#include <stdint.h>

#define N_TOK 4096
#define D_IN  512
#define E_EXP 8
#define TOPK  2
#define H_DIM 2048

#define BM 128
#define BN 64
#define BK 64
#define SLOTS (N_TOK*TOPK + E_EXP*BM)   // 9216 padded slots

// stage: A1[128x64]B A2 | B1[64x64]B B2  (int8, 64B rows, XOR-swizzled)
#define OA1 0
#define OA2 8192
#define OB1 16384
#define OB2 20480
#define STAGE_BYTES 24576
#define NSTAGE 3
#define SMEM_BYTES (NSTAGE * STAGE_BYTES)   // 73728

// -------- scratch --------
__device__ int    g_counts[E_EXP];
__device__ int    g_cnt2[E_EXP];
__device__ int    g_off[E_EXP + 1];
__device__ int    g_slot_tok[SLOTS];
__device__ float  g_slot_w[SLOTS];
__device__ int    g_tok_slot[N_TOK * TOPK];
__device__ float  g_topw[N_TOK * TOPK];
__device__ int    g_topi[N_TOK * TOPK];

__device__ int8_t gxq1[(size_t)N_TOK * D_IN];
__device__ int8_t gxq2[(size_t)N_TOK * D_IN];
__device__ float  g_xs[N_TOK];
__device__ int8_t gW1q1[(size_t)E_EXP * H_DIM * D_IN];  // [e][n][k]
__device__ int8_t gW1q2[(size_t)E_EXP * H_DIM * D_IN];
__device__ float  g_w1s[E_EXP * H_DIM];
__device__ int8_t gW2q1[(size_t)E_EXP * D_IN * H_DIM];  // [e][n][k]
__device__ int8_t gW2q2[(size_t)E_EXP * D_IN * H_DIM];
__device__ float  g_w2s[E_EXP * D_IN];
__device__ float  g_hidden[(size_t)SLOTS * H_DIM];      // 75.5 MB fp32
__device__ int8_t ghq1[(size_t)SLOTS * H_DIM];
__device__ int8_t ghq2[(size_t)SLOTS * H_DIM];
__device__ float  g_hs[SLOTS];
__device__ float  g_ybuf[(size_t)SLOTS * D_IN];

// -------- helpers --------
__device__ __forceinline__ void cp16(uint32_t dst, const void* src, int srcBytes) {
    asm volatile("cp.async.cg.shared.global [%0], [%1], 16, %2;"
                 :: "r"(dst), "l"(src), "r"(srcBytes) : "memory");
}
__device__ __forceinline__ void cp_commit() {
    asm volatile("cp.async.commit_group;" ::: "memory");
}
template<int N> __device__ __forceinline__ void cp_wait() {
    asm volatile("cp.async.wait_group %0;" :: "n"(N) : "memory");
}
__device__ __forceinline__ void ldsm4(uint32_t* r, uint32_t addr) {
    asm volatile("ldmatrix.sync.aligned.m8n8.x4.shared.b16 {%0,%1,%2,%3}, [%4];"
                 : "=r"(r[0]), "=r"(r[1]), "=r"(r[2]), "=r"(r[3]) : "r"(addr));
}
__device__ __forceinline__ void imma(int d[4],
                                     uint32_t a0, uint32_t a1, uint32_t a2, uint32_t a3,
                                     uint32_t b0, uint32_t b1) {
    asm volatile(
        "mma.sync.aligned.m16n8k32.row.col.s32.s8.s8.s32 "
        "{%0,%1,%2,%3},{%4,%5,%6,%7},{%8,%9},{%0,%1,%2,%3};"
        : "+r"(d[0]), "+r"(d[1]), "+r"(d[2]), "+r"(d[3])
        : "r"(a0), "r"(a1), "r"(a2), "r"(a3), "r"(b0), "r"(b1));
}
// swizzled byte offset of 16B chunk c (0..3) in 64B row r
__device__ __forceinline__ uint32_t swz(int r, int c) {
    return (uint32_t)(r * 64 + ((c ^ ((r >> 1) & 3)) * 16));
}
__device__ __forceinline__ void quant2(float v, float inv, int8_t& c1, int8_t& c2) {
    int q  = __float2int_rn(v * inv);
    int q1 = (q + 128) >> 8;
    c1 = (int8_t)q1;
    c2 = (int8_t)(q - (q1 << 8));
}

// -------- 1: per-(e,n) weight absmax (both matrices) --------
__global__ void wmax_all_kernel(const float* __restrict__ W1,
                                const float* __restrict__ W2) {
    int z = blockIdx.z;
    int n = blockIdx.x * blockDim.x + threadIdx.x;
    if (z < E_EXP) {
        if (n >= H_DIM) return;
        const float* s = W1 + (size_t)z * D_IN * H_DIM;
        float m = 1e-20f;
        for (int k = 0; k < D_IN; k++) m = fmaxf(m, fabsf(s[(size_t)k * H_DIM + n]));
        g_w1s[z * H_DIM + n] = m * (1.f / 32512.f);
    } else {
        if (n >= D_IN) return;
        int e = z - E_EXP;
        const float* s = W2 + (size_t)e * H_DIM * D_IN;
        float m = 1e-20f;
        for (int k = 0; k < H_DIM; k++) m = fmaxf(m, fabsf(s[(size_t)k * D_IN + n]));
        g_w2s[e * D_IN + n] = m * (1.f / 32512.f);
    }
}

// -------- 2: transpose + quantize weights (both matrices) --------
__global__ void quant_wt_kernel(const float* __restrict__ W1,
                                const float* __restrict__ W2) {
    int z = blockIdx.z;
    const float* src; const float* ws; int8_t *d1, *d2; int K, N, e;
    if (z < E_EXP) { e = z;         src = W1; ws = g_w1s; d1 = gW1q1; d2 = gW1q2; K = D_IN;  N = H_DIM; }
    else           { e = z - E_EXP; src = W2; ws = g_w2s; d1 = gW2q1; d2 = gW2q2; K = H_DIM; N = D_IN;  }
    int n0 = blockIdx.x * 32, k0 = blockIdx.y * 32;
    if (n0 >= N || k0 >= K) return;

    __shared__ float t[32][33];
    const float* s = src + (size_t)e * K * N;
    int tx = threadIdx.x & 31, ty = threadIdx.x >> 5;
#pragma unroll
    for (int i = 0; i < 4; i++)
        t[ty + 8 * i][tx] = s[(size_t)(k0 + ty + 8 * i) * N + n0 + tx];
    __syncthreads();
    size_t ob = (size_t)e * K * N;
#pragma unroll
    for (int i = 0; i < 4; i++) {
        int n = n0 + ty + 8 * i, k = k0 + tx;
        float inv = 1.f / ws[e * N + n];
        int8_t q1, q2;
        quant2(t[tx][ty + 8 * i], inv, q1, q2);
        size_t o = ob + (size_t)n * K + k;
        d1[o] = q1; d2[o] = q2;
    }
}

// -------- 3: quantize x (warp/row) + routing-state init --------
__global__ void quant_x_kernel(const float* __restrict__ x) {
    int gid = blockIdx.x * blockDim.x + threadIdx.x;
    if (gid < SLOTS) g_slot_tok[gid] = -1;
    if (gid < E_EXP) { g_counts[gid] = 0; g_cnt2[gid] = 0; }

    int row  = gid >> 5;
    int lane = threadIdx.x & 31;
    if (row >= N_TOK) return;
    const float* xr = x + (size_t)row * D_IN;
    float4 v[4];
    float m = 1e-20f;
#pragma unroll
    for (int i = 0; i < 4; i++) {
        v[i] = *(const float4*)(xr + i * 128 + lane * 4);
        m = fmaxf(m, fmaxf(fmaxf(fabsf(v[i].x), fabsf(v[i].y)),
                           fmaxf(fabsf(v[i].z), fabsf(v[i].w))));
    }
#pragma unroll
    for (int o = 16; o > 0; o >>= 1) m = fmaxf(m, __shfl_xor_sync(0xffffffffu, m, o));
    float s = m * (1.f / 32512.f);
    float inv = 1.f / s;
    if (lane == 0) g_xs[row] = s;
#pragma unroll
    for (int i = 0; i < 4; i++) {
        char4 a, b;
        quant2(v[i].x, inv, (int8_t&)a.x, (int8_t&)b.x);
        quant2(v[i].y, inv, (int8_t&)a.y, (int8_t&)b.y);
        quant2(v[i].z, inv, (int8_t&)a.z, (int8_t&)b.z);
        quant2(v[i].w, inv, (int8_t&)a.w, (int8_t&)b.w);
        size_t o = (size_t)row * D_IN + i * 128 + lane * 4;
        *(char4*)(gxq1 + o) = a;
        *(char4*)(gxq2 + o) = b;
    }
}

// -------- 4: gating --------
__global__ void gate_kernel(const float* __restrict__ x,
                            const float* __restrict__ Wg,
                            const float* __restrict__ bg,
                            float* __restrict__ gates_out) {
    int t    = (blockIdx.x * blockDim.x + threadIdx.x) >> 5;
    int lane = threadIdx.x & 31;
    if (t >= N_TOK) return;
    const float* xr = x + (size_t)t * D_IN;

    float acc[E_EXP];
#pragma unroll
    for (int e = 0; e < E_EXP; e++) acc[e] = 0.f;
#pragma unroll
    for (int i = 0; i < 4; i++) {
        int d0 = i * 128 + lane * 4;
        float4 xv = *(const float4*)(xr + d0);
        float xs[4] = {xv.x, xv.y, xv.z, xv.w};
#pragma unroll
        for (int j = 0; j < 4; j++) {
            const float4* wr = (const float4*)(Wg + (d0 + j) * E_EXP);
            float4 w0 = wr[0], w1 = wr[1];
            acc[0] = fmaf(xs[j], w0.x, acc[0]); acc[1] = fmaf(xs[j], w0.y, acc[1]);
            acc[2] = fmaf(xs[j], w0.z, acc[2]); acc[3] = fmaf(xs[j], w0.w, acc[3]);
            acc[4] = fmaf(xs[j], w1.x, acc[4]); acc[5] = fmaf(xs[j], w1.y, acc[5]);
            acc[6] = fmaf(xs[j], w1.z, acc[6]); acc[7] = fmaf(xs[j], w1.w, acc[7]);
        }
    }
#pragma unroll
    for (int o = 16; o > 0; o >>= 1) {
#pragma unroll
        for (int e = 0; e < E_EXP; e++)
            acc[e] += __shfl_xor_sync(0xffffffffu, acc[e], o);
    }
    if (lane == 0) {
        float l[E_EXP], p[E_EXP];
        float m = -1e30f;
#pragma unroll
        for (int e = 0; e < E_EXP; e++) { l[e] = acc[e] + bg[e]; m = fmaxf(m, l[e]); }
        float s = 0.f;
#pragma unroll
        for (int e = 0; e < E_EXP; e++) { p[e] = __expf(l[e] - m); s += p[e]; }
        float inv = 1.f / s;
#pragma unroll
        for (int e = 0; e < E_EXP; e++) p[e] *= inv;
        if (gates_out) {
#pragma unroll
            for (int e = 0; e < E_EXP; e++) gates_out[t * E_EXP + e] = p[e];
        }
        int i1 = 0; float p1 = p[0];
#pragma unroll
        for (int e = 1; e < E_EXP; e++) if (p[e] > p1) { p1 = p[e]; i1 = e; }
        int i2 = -1; float p2 = -1.f;
#pragma unroll
        for (int e = 0; e < E_EXP; e++) if (e != i1 && p[e] > p2) { p2 = p[e]; i2 = e; }
        g_topw[t * 2 + 0] = p1;  g_topi[t * 2 + 0] = i1;
        g_topw[t * 2 + 1] = p2;  g_topi[t * 2 + 1] = i2;
        atomicAdd(&g_counts[i1], 1);
        atomicAdd(&g_counts[i2], 1);
    }
}

// -------- 5: scatter (scan folded in) --------
__global__ void scatter_kernel() {
    __shared__ int soff[E_EXP + 1];
    if (threadIdx.x == 0) {
        int o = 0;
#pragma unroll
        for (int e = 0; e < E_EXP; e++) {
            soff[e] = o;
            o += ((g_counts[e] + BM - 1) / BM) * BM;
        }
        soff[E_EXP] = o;
        if (blockIdx.x == 0) {
#pragma unroll
            for (int e = 0; e <= E_EXP; e++) g_off[e] = soff[e];
        }
    }
    __syncthreads();
    int i = blockIdx.x * blockDim.x + threadIdx.x;
    if (i >= N_TOK * TOPK) return;
    int e = g_topi[i];
    int pos = soff[e] + atomicAdd(&g_cnt2[e], 1);
    g_slot_tok[pos] = i >> 1;
    g_slot_w[pos]   = g_topw[i];
    g_tok_slot[i]   = pos;
}

// -------- 7: quantize hidden (warp/row, two-pass) --------
__global__ void quant_h_kernel() {
    int row  = (blockIdx.x * blockDim.x + threadIdx.x) >> 5;
    int lane = threadIdx.x & 31;
    if (row >= SLOTS) return;
    const float* hr = g_hidden + (size_t)row * H_DIM;
    float m = 1e-20f;
#pragma unroll
    for (int i = 0; i < 16; i++) {
        float4 v = *(const float4*)(hr + i * 128 + lane * 4);
        m = fmaxf(m, fmaxf(fmaxf(fabsf(v.x), fabsf(v.y)),
                           fmaxf(fabsf(v.z), fabsf(v.w))));
    }
#pragma unroll
    for (int o = 16; o > 0; o >>= 1) m = fmaxf(m, __shfl_xor_sync(0xffffffffu, m, o));
    float s = m * (1.f / 32512.f);
    float inv = 1.f / s;
    if (lane == 0) g_hs[row] = s;
#pragma unroll
    for (int i = 0; i < 16; i++) {
        float4 v = *(const float4*)(hr + i * 128 + lane * 4);
        char4 a, b;
        quant2(v.x, inv, (int8_t&)a.x, (int8_t&)b.x);
        quant2(v.y, inv, (int8_t&)a.y, (int8_t&)b.y);
        quant2(v.z, inv, (int8_t&)a.z, (int8_t&)b.z);
        quant2(v.w, inv, (int8_t&)a.w, (int8_t&)b.w);
        size_t o = (size_t)row * H_DIM + i * 128 + lane * 4;
        *(char4*)(ghq1 + o) = a;
        *(char4*)(ghq2 + o) = b;
    }
}

// -------- grouped dual-int8 IMMA GEMM --------
template<int KTOT, int NTOT, bool GATHER, bool RELU, bool SCALE>
__global__ void __launch_bounds__(256, 2)
imma_gemm_kernel(const int8_t* __restrict__ Aq1, const int8_t* __restrict__ Aq2,
                 const float* __restrict__ Ascale,
                 const int8_t* __restrict__ Bq1, const int8_t* __restrict__ Bq2,
                 const float* __restrict__ Bscale,
                 const float* __restrict__ Bias)
{
    constexpr int KT = KTOT / BK;
    extern __shared__ char smem[];
    __shared__ float sASc[BM];
    __shared__ float sW[BM];
    __shared__ int   sTok[BM];

    const int m0 = blockIdx.y * BM;
    const int n0 = blockIdx.x * BN;
    if (m0 >= g_off[E_EXP]) return;
    int e = 0;
#pragma unroll
    for (int i = 1; i < E_EXP; i++) if (m0 >= g_off[i]) e = i;

    const int tid = threadIdx.x;
    if (tid < BM) {
        if (GATHER) {
            int tok = g_slot_tok[m0 + tid];
            sTok[tid]  = tok;
            sASc[tid]  = (tok >= 0) ? Ascale[tok] : 0.f;
        } else {
            sASc[tid] = Ascale[m0 + tid];
        }
        if (SCALE) sW[tid] = g_slot_w[m0 + tid];
    }
    __syncthreads();

    const int8_t* Bp1 = Bq1 + (size_t)e * NTOT * KTOT;
    const int8_t* Bp2 = Bq2 + (size_t)e * NTOT * KTOT;
    const float*  Bs  = Bscale + e * NTOT;

    // ---- staging
    const int arow = tid >> 1;
    const int akoff = (tid & 1) * 32;
    const int8_t *ap1, *ap2;
    int abytes = 16;
    if (GATHER) {
        int tok = sTok[arow];
        if (tok >= 0) { ap1 = Aq1 + (size_t)tok * KTOT + akoff; ap2 = Aq2 + (size_t)tok * KTOT + akoff; }
        else          { ap1 = Aq1; ap2 = Aq2; abytes = 0; }
    } else {
        ap1 = Aq1 + (size_t)(m0 + arow) * KTOT + akoff;
        ap2 = Aq2 + (size_t)(m0 + arow) * KTOT + akoff;
    }
    const int brow = tid >> 2;
    const int bko  = (tid & 3) * 16;
    const int8_t* bp1 = Bp1 + (size_t)(n0 + brow) * KTOT + bko;
    const int8_t* bp2 = Bp2 + (size_t)(n0 + brow) * KTOT + bko;

    const uint32_t sbase = (uint32_t)__cvta_generic_to_shared(smem);
    const uint32_t da0 = swz(arow, (tid & 1) * 2);
    const uint32_t da1 = swz(arow, (tid & 1) * 2 + 1);
    const uint32_t db  = swz(brow, tid & 3);

    auto stage = [&](int buf, int k0) {
        uint32_t sb = sbase + buf * STAGE_BYTES;
        cp16(sb + OA1 + da0, ap1 + k0,      abytes);
        cp16(sb + OA1 + da1, ap1 + k0 + 16, abytes);
        cp16(sb + OA2 + da0, ap2 + k0,      abytes);
        cp16(sb + OA2 + da1, ap2 + k0 + 16, abytes);
        cp16(sb + OB1 + db,  bp1 + k0, 16);
        cp16(sb + OB2 + db,  bp2 + k0, 16);
        cp_commit();
    };

    // ---- fragment addressing
    const int lane = tid & 31;
    const int wm = (tid >> 5) >> 2;   // 0..1
    const int wn = (tid >> 5) & 3;    // 0..3
    const int g  = lane >> 3;
    const int lr = lane & 7;

    const int arl = wm * 64 + lr + (g & 1) * 8;
    uint32_t aoff[2];
#pragma unroll
    for (int ks = 0; ks < 2; ks++)
        aoff[ks] = (uint32_t)(arl * 64) + (((uint32_t)(ks * 2 + (g >> 1)) ^ ((uint32_t)(arl >> 1) & 3)) * 16);

    const int brl = wn * 16 + lr + (g >> 1) * 8;
    uint32_t boff[2];
#pragma unroll
    for (int ks = 0; ks < 2; ks++)
        boff[ks] = (uint32_t)(brl * 64) + (((uint32_t)(ks * 2 + (g & 1)) ^ ((uint32_t)(brl >> 1) & 3)) * 16);

    int acc11[4][2][4], acc12[4][2][4];
#pragma unroll
    for (int mt = 0; mt < 4; mt++)
#pragma unroll
        for (int nt = 0; nt < 2; nt++)
#pragma unroll
            for (int i = 0; i < 4; i++) { acc11[mt][nt][i] = 0; acc12[mt][nt][i] = 0; }

    stage(0, 0);
    stage(1, BK);
    int buf = 0;
    for (int kt = 0; kt < KT; kt++) {
        if (kt < KT - 1) cp_wait<1>(); else cp_wait<0>();
        __syncthreads();
        if (kt + 2 < KT) {
            int nb = buf + 2; if (nb >= NSTAGE) nb -= NSTAGE;
            stage(nb, (kt + 2) * BK);
        }
        const uint32_t sb = sbase + buf * STAGE_BYTES;
#pragma unroll
        for (int ks = 0; ks < 2; ks++) {
            uint32_t b1f[4], b2f[4];   // [nt0 b0, nt0 b1, nt1 b0, nt1 b1]
            ldsm4(b1f, sb + OB1 + boff[ks]);
            ldsm4(b2f, sb + OB2 + boff[ks]);
#pragma unroll
            for (int mt = 0; mt < 4; mt++) {
                uint32_t a1[4], a2[4];
                ldsm4(a1, sb + OA1 + aoff[ks] + mt * 1024);
                ldsm4(a2, sb + OA2 + aoff[ks] + mt * 1024);
#pragma unroll
                for (int nt = 0; nt < 2; nt++) {
                    imma(acc11[mt][nt], a1[0], a1[1], a1[2], a1[3], b1f[nt * 2], b1f[nt * 2 + 1]);
                    imma(acc12[mt][nt], a1[0], a1[1], a1[2], a1[3], b2f[nt * 2], b2f[nt * 2 + 1]);
                    imma(acc12[mt][nt], a2[0], a2[1], a2[2], a2[3], b1f[nt * 2], b1f[nt * 2 + 1]);
                }
            }
        }
        buf++; if (buf >= NSTAGE) buf = 0;
    }

    const int r = lane >> 2;
    const int c = lane & 3;
    const float* bias = Bias + (size_t)e * NTOT;
#pragma unroll
    for (int mt = 0; mt < 4; mt++) {
        int row0 = m0 + wm * 64 + mt * 16 + r;
        int lrow = wm * 64 + mt * 16 + r;
        float sa0 = sASc[lrow], sa1 = sASc[lrow + 8];
#pragma unroll
        for (int nt = 0; nt < 2; nt++) {
            int col = n0 + wn * 16 + nt * 8 + 2 * c;
            float sb0 = Bs[col], sb1 = Bs[col + 1];
            float b0v = bias[col], b1v = bias[col + 1];
            float v0 = sa0 * sb0 * (65536.f * (float)acc11[mt][nt][0] + 256.f * (float)acc12[mt][nt][0]) + b0v;
            float v1 = sa0 * sb1 * (65536.f * (float)acc11[mt][nt][1] + 256.f * (float)acc12[mt][nt][1]) + b1v;
            float v2 = sa1 * sb0 * (65536.f * (float)acc11[mt][nt][2] + 256.f * (float)acc12[mt][nt][2]) + b0v;
            float v3 = sa1 * sb1 * (65536.f * (float)acc11[mt][nt][3] + 256.f * (float)acc12[mt][nt][3]) + b1v;
            if (RELU) {
                v0 = fmaxf(v0, 0.f); v1 = fmaxf(v1, 0.f);
                v2 = fmaxf(v2, 0.f); v3 = fmaxf(v3, 0.f);
                float* o0 = g_hidden + (size_t)row0 * NTOT + col;
                *(float2*)o0 = make_float2(v0, v1);
                *(float2*)(o0 + (size_t)8 * NTOT) = make_float2(v2, v3);
            } else {
                float w0 = SCALE ? sW[lrow]     : 1.f;
                float w1 = SCALE ? sW[lrow + 8] : 1.f;
                float* o0 = g_ybuf + (size_t)row0 * NTOT + col;
                *(float2*)o0 = make_float2(v0 * w0, v1 * w0);
                *(float2*)(o0 + (size_t)8 * NTOT) = make_float2(v2 * w1, v3 * w1);
            }
        }
    }
}

// -------- 9: deterministic combine --------
__global__ void combine_kernel(float* __restrict__ out) {
    int i = blockIdx.x * blockDim.x + threadIdx.x;
    if (i >= N_TOK * (D_IN / 4)) return;
    int t  = i >> 7;
    int dd = (i & 127) << 2;
    int s0 = g_tok_slot[t * 2 + 0];
    int s1 = g_tok_slot[t * 2 + 1];
    float4 a = *(const float4*)(g_ybuf + (size_t)s0 * D_IN + dd);
    float4 b = *(const float4*)(g_ybuf + (size_t)s1 * D_IN + dd);
    float4 r = make_float4(a.x + b.x, a.y + b.y, a.z + b.z, a.w + b.w);
    *(float4*)(out + (size_t)t * D_IN + dd) = r;
}

extern "C" void kernel_launch(void* const* d_in, const int* in_sizes, int n_in,
                              void* d_out, int out_size) {
    const float* x  = (const float*)d_in[0];
    const float* Wg = (const float*)d_in[1];
    const float* bg = (const float*)d_in[2];
    const float* W1 = (const float*)d_in[3];
    const float* b1 = (const float*)d_in[4];
    const float* W2 = (const float*)d_in[5];
    const float* b2 = (const float*)d_in[6];
    float* out = (float*)d_out;

    float* gates_out = nullptr;
    if (out_size >= N_TOK * D_IN + N_TOK * E_EXP)
        gates_out = out + (size_t)N_TOK * D_IN;

    cudaFuncSetAttribute(imma_gemm_kernel<D_IN, H_DIM, true, true, false>,
                         cudaFuncAttributeMaxDynamicSharedMemorySize, SMEM_BYTES);
    cudaFuncSetAttribute(imma_gemm_kernel<H_DIM, D_IN, false, false, true>,
                         cudaFuncAttributeMaxDynamicSharedMemorySize, SMEM_BYTES);

    int8_t *xq1, *xq2, *w1q1, *w1q2, *w2q1, *w2q2, *hq1, *hq2;
    float *xs, *w1s, *w2s, *hs;
    cudaGetSymbolAddress((void**)&xq1, gxq1);
    cudaGetSymbolAddress((void**)&xq2, gxq2);
    cudaGetSymbolAddress((void**)&xs,  g_xs);
    cudaGetSymbolAddress((void**)&w1q1, gW1q1);
    cudaGetSymbolAddress((void**)&w1q2, gW1q2);
    cudaGetSymbolAddress((void**)&w1s,  g_w1s);
    cudaGetSymbolAddress((void**)&w2q1, gW2q1);
    cudaGetSymbolAddress((void**)&w2q2, gW2q2);
    cudaGetSymbolAddress((void**)&w2s,  g_w2s);
    cudaGetSymbolAddress((void**)&hq1, ghq1);
    cudaGetSymbolAddress((void**)&hq2, ghq2);
    cudaGetSymbolAddress((void**)&hs,  g_hs);

    // 1: weight absmax (both)
    wmax_all_kernel<<<dim3(H_DIM / 256, 1, 2 * E_EXP), 256>>>(W1, W2);
    // 2: weight transpose+quant (both)
    quant_wt_kernel<<<dim3(H_DIM / 32, H_DIM / 32, 2 * E_EXP), 256>>>(W1, W2);
    // 3: x quant + routing init
    quant_x_kernel<<<(N_TOK * 32 + 255) / 256, 256>>>(x);
    // 4: gate
    gate_kernel<<<(N_TOK * 32 + 255) / 256, 256>>>(x, Wg, bg, gates_out);
    // 5: scatter
    scatter_kernel<<<(N_TOK * TOPK + 255) / 256, 256>>>();
    // 6: GEMM1 (profiled slot)
    dim3 g1(H_DIM / BN, SLOTS / BM);   // (32, 72)
    imma_gemm_kernel<D_IN, H_DIM, true, true, false>
        <<<g1, 256, SMEM_BYTES>>>(xq1, xq2, xs, w1q1, w1q2, w1s, b1);
    // 7: hidden quant
    quant_h_kernel<<<(SLOTS * 32 + 255) / 256, 256>>>();
    // 8: GEMM2
    dim3 g2(D_IN / BN, SLOTS / BM);    // (8, 72)
    imma_gemm_kernel<H_DIM, D_IN, false, false, true>
        <<<g2, 256, SMEM_BYTES>>>(hq1, hq2, hs, w2q1, w2q2, w2s, b2);
    // 9: combine
    combine_kernel<<<(N_TOK * (D_IN / 4) + 255) / 256, 256>>>(out);
}

// round 9
// speedup vs baseline: 2.1495x; 2.1495x over previous
#include <cuda_runtime.h>
#include <cuda_bf16.h>
#include <math.h>
#include <stdint.h>

#define N_TOK 4096
#define D_IN  512
#define E_EXP 8
#define TOPK  2
#define H_DIM 2048

#define BM 128
#define BN 128
#define BK 32
#define SLOTS (N_TOK*TOPK + E_EXP*BM)   // 9216 padded slots

// smem: 4 planes (Ah, Al, Bh, Bl), each 128 rows x 32 bf16 (64B/row), XOR-swizzled
#define PLANE_BYTES 8192
#define OAH 0
#define OAL 8192
#define OBH 16384
#define OBL 24576
#define STAGE_BYTES 32768
#define NSTAGE 3
#define SMEM_BYTES (NSTAGE * STAGE_BYTES)   // 98304

// -------- scratch (device globals; no allocation allowed) --------
__device__ int   g_counts[E_EXP];
__device__ int   g_cnt2[E_EXP];
__device__ int   g_off[E_EXP + 1];
__device__ int   g_slot_tok[SLOTS];
__device__ float g_slot_w[SLOTS];
__device__ int   g_tok_slot[N_TOK * TOPK];
__device__ float g_topw[N_TOK * TOPK];
__device__ int   g_topi[N_TOK * TOPK];

__device__ __nv_bfloat16 gx_hi[(size_t)N_TOK * D_IN];
__device__ __nv_bfloat16 gx_lo[(size_t)N_TOK * D_IN];
__device__ __nv_bfloat16 gW1t_hi[(size_t)E_EXP * H_DIM * D_IN]; // [e][n][k]
__device__ __nv_bfloat16 gW1t_lo[(size_t)E_EXP * H_DIM * D_IN];
__device__ __nv_bfloat16 gW2t_hi[(size_t)E_EXP * D_IN * H_DIM]; // [e][n][k]
__device__ __nv_bfloat16 gW2t_lo[(size_t)E_EXP * D_IN * H_DIM];
__device__ __nv_bfloat16 gh_hi[(size_t)SLOTS * H_DIM];
__device__ __nv_bfloat16 gh_lo[(size_t)SLOTS * H_DIM];
__device__ float g_ybuf[(size_t)SLOTS * D_IN];

// -------- helpers --------
__device__ __forceinline__ void cp16(uint32_t dst, const void* src, int srcBytes) {
    asm volatile("cp.async.cg.shared.global [%0], [%1], 16, %2;"
                 :: "r"(dst), "l"(src), "r"(srcBytes) : "memory");
}
__device__ __forceinline__ void cp_commit() {
    asm volatile("cp.async.commit_group;" ::: "memory");
}
template<int N> __device__ __forceinline__ void cp_wait() {
    asm volatile("cp.async.wait_group %0;" :: "n"(N) : "memory");
}
__device__ __forceinline__ void ldsm4(uint32_t* r, uint32_t addr) {
    asm volatile("ldmatrix.sync.aligned.m8n8.x4.shared.b16 {%0,%1,%2,%3}, [%4];"
                 : "=r"(r[0]), "=r"(r[1]), "=r"(r[2]), "=r"(r[3]) : "r"(addr));
}
__device__ __forceinline__ void mma_bf16(float d[4],
                                         uint32_t a0, uint32_t a1, uint32_t a2, uint32_t a3,
                                         uint32_t b0, uint32_t b1) {
    asm volatile(
        "mma.sync.aligned.m16n8k16.row.col.f32.bf16.bf16.f32 "
        "{%0,%1,%2,%3},{%4,%5,%6,%7},{%8,%9},{%0,%1,%2,%3};"
        : "+f"(d[0]), "+f"(d[1]), "+f"(d[2]), "+f"(d[3])
        : "r"(a0), "r"(a1), "r"(a2), "r"(a3), "r"(b0), "r"(b1));
}
// swizzled byte offset of 16B chunk c (0..3) in row r of a plane
__device__ __forceinline__ uint32_t swz(int r, int c) {
    return (uint32_t)(r * 64 + ((c ^ ((r >> 1) & 3)) * 16));
}
__device__ __forceinline__ uint32_t pack2(float a, float b) {
    __nv_bfloat162 h;
    h.x = __float2bfloat16(a);
    h.y = __float2bfloat16(b);
    return *(uint32_t*)&h;
}

// -------- 1: fused W1+W2 transpose/split + routing-state init --------
// z<E_EXP: W1 (K=512, N=2048); else W2 (K=2048, N=512).
__global__ void split_wt_all_kernel(const float* __restrict__ W1,
                                    const float* __restrict__ W2) {
    if (blockIdx.z == 0 && blockIdx.y == 0) {
        int idx = blockIdx.x * blockDim.x + threadIdx.x;
        if (idx < SLOTS) g_slot_tok[idx] = -1;
        if (idx < E_EXP) { g_counts[idx] = 0; g_cnt2[idx] = 0; }
    }
    int z = blockIdx.z;
    const float* src; __nv_bfloat16 *dhi, *dlo; int K, N, e;
    if (z < E_EXP) { e = z;         src = W1; dhi = gW1t_hi; dlo = gW1t_lo; K = D_IN;  N = H_DIM; }
    else           { e = z - E_EXP; src = W2; dhi = gW2t_hi; dlo = gW2t_lo; K = H_DIM; N = D_IN;  }
    int n0 = blockIdx.x * 32, k0 = blockIdx.y * 32;
    if (n0 >= N || k0 >= K) return;

    __shared__ float t[32][33];
    const float* s = src + (size_t)e * K * N;
    int tx = threadIdx.x & 31, ty = threadIdx.x >> 5;
#pragma unroll
    for (int i = 0; i < 4; i++)
        t[ty + 8 * i][tx] = s[(size_t)(k0 + ty + 8 * i) * N + n0 + tx];
    __syncthreads();
    size_t ob = (size_t)e * K * N;
#pragma unroll
    for (int i = 0; i < 4; i++) {
        int n = n0 + ty + 8 * i, k = k0 + tx;
        float v = t[tx][ty + 8 * i];
        __nv_bfloat16 h = __float2bfloat16(v);
        dhi[ob + (size_t)n * K + k] = h;
        dlo[ob + (size_t)n * K + k] = __float2bfloat16(v - __bfloat162float(h));
    }
}

// -------- 2: gating + x hi/lo split (one warp per token) --------
__global__ void gate_kernel(const float* __restrict__ x,
                            const float* __restrict__ Wg,
                            const float* __restrict__ bg,
                            float* __restrict__ gates_out) {
    int t    = (blockIdx.x * blockDim.x + threadIdx.x) >> 5;
    int lane = threadIdx.x & 31;
    if (t >= N_TOK) return;
    const float* xr = x + (size_t)t * D_IN;

    float acc[E_EXP];
#pragma unroll
    for (int e = 0; e < E_EXP; e++) acc[e] = 0.f;
#pragma unroll
    for (int i = 0; i < 4; i++) {
        int d0 = i * 128 + lane * 4;
        float4 xv = *(const float4*)(xr + d0);
        // split/store
        uint32_t h0 = pack2(xv.x, xv.y), h1 = pack2(xv.z, xv.w);
        __nv_bfloat162* hp = (__nv_bfloat162*)&h0;
        __nv_bfloat162* hp1 = (__nv_bfloat162*)&h1;
        uint32_t l0 = pack2(xv.x - __bfloat162float(hp->x),  xv.y - __bfloat162float(hp->y));
        uint32_t l1 = pack2(xv.z - __bfloat162float(hp1->x), xv.w - __bfloat162float(hp1->y));
        size_t o = (size_t)t * D_IN + d0;
        *(uint2*)(gx_hi + o) = make_uint2(h0, h1);
        *(uint2*)(gx_lo + o) = make_uint2(l0, l1);
        // gate accumulate
        float xs[4] = {xv.x, xv.y, xv.z, xv.w};
#pragma unroll
        for (int j = 0; j < 4; j++) {
            const float4* wr = (const float4*)(Wg + (d0 + j) * E_EXP);
            float4 w0 = wr[0], w1 = wr[1];
            acc[0] = fmaf(xs[j], w0.x, acc[0]); acc[1] = fmaf(xs[j], w0.y, acc[1]);
            acc[2] = fmaf(xs[j], w0.z, acc[2]); acc[3] = fmaf(xs[j], w0.w, acc[3]);
            acc[4] = fmaf(xs[j], w1.x, acc[4]); acc[5] = fmaf(xs[j], w1.y, acc[5]);
            acc[6] = fmaf(xs[j], w1.z, acc[6]); acc[7] = fmaf(xs[j], w1.w, acc[7]);
        }
    }
#pragma unroll
    for (int o = 16; o > 0; o >>= 1) {
#pragma unroll
        for (int e = 0; e < E_EXP; e++)
            acc[e] += __shfl_xor_sync(0xffffffffu, acc[e], o);
    }
    if (lane == 0) {
        float l[E_EXP], p[E_EXP];
        float m = -1e30f;
#pragma unroll
        for (int e = 0; e < E_EXP; e++) { l[e] = acc[e] + bg[e]; m = fmaxf(m, l[e]); }
        float s = 0.f;
#pragma unroll
        for (int e = 0; e < E_EXP; e++) { p[e] = __expf(l[e] - m); s += p[e]; }
        float inv = 1.f / s;
#pragma unroll
        for (int e = 0; e < E_EXP; e++) p[e] *= inv;
        if (gates_out) {
#pragma unroll
            for (int e = 0; e < E_EXP; e++) gates_out[t * E_EXP + e] = p[e];
        }
        int i1 = 0; float p1 = p[0];
#pragma unroll
        for (int e = 1; e < E_EXP; e++) if (p[e] > p1) { p1 = p[e]; i1 = e; }
        int i2 = -1; float p2 = -1.f;
#pragma unroll
        for (int e = 0; e < E_EXP; e++) if (e != i1 && p[e] > p2) { p2 = p[e]; i2 = e; }
        g_topw[t * 2 + 0] = p1;  g_topi[t * 2 + 0] = i1;
        g_topw[t * 2 + 1] = p2;  g_topi[t * 2 + 1] = i2;
        atomicAdd(&g_counts[i1], 1);
        atomicAdd(&g_counts[i2], 1);
    }
}

// -------- 3: scatter (scan folded in) --------
__global__ void scatter_kernel() {
    __shared__ int soff[E_EXP + 1];
    if (threadIdx.x == 0) {
        int o = 0;
#pragma unroll
        for (int e = 0; e < E_EXP; e++) {
            soff[e] = o;
            o += ((g_counts[e] + BM - 1) / BM) * BM;
        }
        soff[E_EXP] = o;
        if (blockIdx.x == 0) {
#pragma unroll
            for (int e = 0; e <= E_EXP; e++) g_off[e] = soff[e];
        }
    }
    __syncthreads();
    int i = blockIdx.x * blockDim.x + threadIdx.x;
    if (i >= N_TOK * TOPK) return;
    int e = g_topi[i];
    int pos = soff[e] + atomicAdd(&g_cnt2[e], 1);
    g_slot_tok[pos] = i >> 1;
    g_slot_w[pos]   = g_topw[i];
    g_tok_slot[i]   = pos;
}

// -------- grouped bf16x3 tensor-core GEMM, 3-stage pipeline --------
template<int KTOT, int NTOT, bool GATHER, bool RELU, bool SCALE>
__global__ void __launch_bounds__(256, 2)
mma_gemm_kernel(const __nv_bfloat16* __restrict__ Ahi,
                const __nv_bfloat16* __restrict__ Alo,
                const __nv_bfloat16* __restrict__ Bthi,
                const __nv_bfloat16* __restrict__ Btlo,
                const float* __restrict__ Bias)
{
    constexpr int KT = KTOT / BK;
    extern __shared__ char smem[];
    __shared__ int   sTok[BM];
    __shared__ float sW[BM];

    const int m0 = blockIdx.y * BM;
    const int n0 = blockIdx.x * BN;
    if (m0 >= g_off[E_EXP]) return;
    int e = 0;
#pragma unroll
    for (int i = 1; i < E_EXP; i++) if (m0 >= g_off[i]) e = i;

    const int tid = threadIdx.x;
    if (tid < BM) {
        if (GATHER) sTok[tid] = g_slot_tok[m0 + tid];
        if (SCALE)  sW[tid]   = g_slot_w[m0 + tid];
    }
    __syncthreads();

    const __nv_bfloat16* Wh = Bthi + (size_t)e * NTOT * KTOT;
    const __nv_bfloat16* Wl = Btlo + (size_t)e * NTOT * KTOT;

    const int srow = tid >> 1;
    const int skoff = (tid & 1) * 16;

    const __nv_bfloat16 *arow_h, *arow_l;
    int abytes = 16;
    if (GATHER) {
        int tok = sTok[srow];
        if (tok >= 0) {
            arow_h = Ahi + (size_t)tok * KTOT + skoff;
            arow_l = Alo + (size_t)tok * KTOT + skoff;
        } else { arow_h = Ahi; arow_l = Alo; abytes = 0; }
    } else {
        arow_h = Ahi + (size_t)(m0 + srow) * KTOT + skoff;
        arow_l = Alo + (size_t)(m0 + srow) * KTOT + skoff;
    }
    const __nv_bfloat16* brow_h = Wh + (size_t)(n0 + srow) * KTOT + skoff;
    const __nv_bfloat16* brow_l = Wl + (size_t)(n0 + srow) * KTOT + skoff;

    const uint32_t sbase = (uint32_t)__cvta_generic_to_shared(smem);
    const uint32_t d0 = swz(srow, 2 * (tid & 1));
    const uint32_t d1 = swz(srow, 2 * (tid & 1) + 1);

    auto stage = [&](int buf, int k0) {
        uint32_t sb = sbase + buf * STAGE_BYTES;
        cp16(sb + OAH + d0, arow_h + k0,     abytes);
        cp16(sb + OAH + d1, arow_h + k0 + 8, abytes);
        cp16(sb + OAL + d0, arow_l + k0,     abytes);
        cp16(sb + OAL + d1, arow_l + k0 + 8, abytes);
        cp16(sb + OBH + d0, brow_h + k0,     16);
        cp16(sb + OBH + d1, brow_h + k0 + 8, 16);
        cp16(sb + OBL + d0, brow_l + k0,     16);
        cp16(sb + OBL + d1, brow_l + k0 + 8, 16);
        cp_commit();
    };

    const int lane = tid & 31;
    const int wm = (tid >> 5) >> 2;  // 0..1
    const int wn = (tid >> 5) & 3;   // 0..3
    const int g  = lane >> 3;
    const int lr = lane & 7;

    const int arow0 = wm * 64 + lr + (g & 1) * 8;
    const uint32_t aswz = ((uint32_t)(arow0 >> 1) & 3);
    uint32_t aoff[2];
#pragma unroll
    for (int ks = 0; ks < 2; ks++)
        aoff[ks] = (uint32_t)(arow0 * 64) + (((uint32_t)(ks * 2 + (g >> 1)) ^ aswz) * 16);

    const int brow0 = wn * 32 + lr + ((g >> 1) & 1) * 8;
    const uint32_t bswz = ((uint32_t)(brow0 >> 1) & 3);
    uint32_t boff[2];
#pragma unroll
    for (int ks = 0; ks < 2; ks++)
        boff[ks] = (uint32_t)(brow0 * 64) + (((uint32_t)(ks * 2 + (g & 1)) ^ bswz) * 16);

    float acc[4][4][4];
#pragma unroll
    for (int mt = 0; mt < 4; mt++)
#pragma unroll
        for (int nt = 0; nt < 4; nt++)
#pragma unroll
            for (int i = 0; i < 4; i++) acc[mt][nt][i] = 0.f;

    stage(0, 0);
    stage(1, BK);
    int buf = 0;
    for (int kt = 0; kt < KT; kt++) {
        if (kt < KT - 1) cp_wait<1>(); else cp_wait<0>();
        __syncthreads();
        if (kt + 2 < KT) {
            int nb = buf + 2; if (nb >= NSTAGE) nb -= NSTAGE;
            stage(nb, (kt + 2) * BK);
        }
        const uint32_t sb = sbase + buf * STAGE_BYTES;
#pragma unroll
        for (int ks = 0; ks < 2; ks++) {
            uint32_t bh[8], bl[8];
#pragma unroll
            for (int np = 0; np < 2; np++) {
                ldsm4(&bh[np * 4], sb + OBH + boff[ks] + np * 1024);
                ldsm4(&bl[np * 4], sb + OBL + boff[ks] + np * 1024);
            }
#pragma unroll
            for (int mt = 0; mt < 4; mt++) {
                uint32_t ah[4], al[4];
                ldsm4(ah, sb + OAH + aoff[ks] + mt * 1024);
                ldsm4(al, sb + OAL + aoff[ks] + mt * 1024);
#pragma unroll
                for (int nt = 0; nt < 4; nt++) {
                    int i0 = (nt >> 1) * 4 + (nt & 1) * 2;
                    uint32_t b0h = bh[i0], b1h = bh[i0 + 1];
                    uint32_t b0l = bl[i0], b1l = bl[i0 + 1];
                    mma_bf16(acc[mt][nt], ah[0], ah[1], ah[2], ah[3], b0h, b1h);
                    mma_bf16(acc[mt][nt], al[0], al[1], al[2], al[3], b0h, b1h);
                    mma_bf16(acc[mt][nt], ah[0], ah[1], ah[2], ah[3], b0l, b1l);
                }
            }
        }
        buf++; if (buf >= NSTAGE) buf = 0;
    }

    const int r = lane >> 2;
    const int c = lane & 3;
    const float* bias = Bias + (size_t)e * NTOT;
#pragma unroll
    for (int mt = 0; mt < 4; mt++) {
        int row0 = m0 + wm * 64 + mt * 16 + r;
        int lrow = wm * 64 + mt * 16 + r;
#pragma unroll
        for (int nt = 0; nt < 4; nt++) {
            int col = n0 + wn * 32 + nt * 8 + 2 * c;
            float b0v = bias[col], b1v = bias[col + 1];
            float v0 = acc[mt][nt][0] + b0v, v1 = acc[mt][nt][1] + b1v;
            float v2 = acc[mt][nt][2] + b0v, v3 = acc[mt][nt][3] + b1v;
            if (RELU) {
                v0 = fmaxf(v0, 0.f); v1 = fmaxf(v1, 0.f);
                v2 = fmaxf(v2, 0.f); v3 = fmaxf(v3, 0.f);
                size_t o0 = (size_t)row0 * NTOT + col;
                size_t o2 = o0 + (size_t)8 * NTOT;
                __nv_bfloat16 h;
                h = __float2bfloat16(v0); gh_hi[o0]     = h; gh_lo[o0]     = __float2bfloat16(v0 - __bfloat162float(h));
                h = __float2bfloat16(v1); gh_hi[o0 + 1] = h; gh_lo[o0 + 1] = __float2bfloat16(v1 - __bfloat162float(h));
                h = __float2bfloat16(v2); gh_hi[o2]     = h; gh_lo[o2]     = __float2bfloat16(v2 - __bfloat162float(h));
                h = __float2bfloat16(v3); gh_hi[o2 + 1] = h; gh_lo[o2 + 1] = __float2bfloat16(v3 - __bfloat162float(h));
            } else {
                float w0 = SCALE ? sW[lrow]     : 1.f;
                float w1 = SCALE ? sW[lrow + 8] : 1.f;
                float* o0 = g_ybuf + (size_t)row0 * NTOT + col;
                *(float2*)o0 = make_float2(v0 * w0, v1 * w0);
                *(float2*)(o0 + (size_t)8 * NTOT) = make_float2(v2 * w1, v3 * w1);
            }
        }
    }
}

// -------- 6: deterministic combine --------
__global__ void combine_kernel(float* __restrict__ out) {
    int i = blockIdx.x * blockDim.x + threadIdx.x;
    if (i >= N_TOK * (D_IN / 4)) return;
    int t  = i >> 7;
    int dd = (i & 127) << 2;
    int s0 = g_tok_slot[t * 2 + 0];
    int s1 = g_tok_slot[t * 2 + 1];
    float4 a = *(const float4*)(g_ybuf + (size_t)s0 * D_IN + dd);
    float4 b = *(const float4*)(g_ybuf + (size_t)s1 * D_IN + dd);
    float4 r = make_float4(a.x + b.x, a.y + b.y, a.z + b.z, a.w + b.w);
    *(float4*)(out + (size_t)t * D_IN + dd) = r;
}

extern "C" void kernel_launch(void* const* d_in, const int* in_sizes, int n_in,
                              void* d_out, int out_size) {
    const float* x  = (const float*)d_in[0];
    const float* Wg = (const float*)d_in[1];
    const float* bg = (const float*)d_in[2];
    const float* W1 = (const float*)d_in[3];
    const float* b1 = (const float*)d_in[4];
    const float* W2 = (const float*)d_in[5];
    const float* b2 = (const float*)d_in[6];
    float* out = (float*)d_out;

    float* gates_out = nullptr;
    if (out_size >= N_TOK * D_IN + N_TOK * E_EXP)
        gates_out = out + (size_t)N_TOK * D_IN;

    cudaFuncSetAttribute(mma_gemm_kernel<D_IN, H_DIM, true, true, false>,
                         cudaFuncAttributeMaxDynamicSharedMemorySize, SMEM_BYTES);
    cudaFuncSetAttribute(mma_gemm_kernel<H_DIM, D_IN, false, false, true>,
                         cudaFuncAttributeMaxDynamicSharedMemorySize, SMEM_BYTES);

    __nv_bfloat16 *xhi, *xlo, *w1h, *w1l, *w2h, *w2l, *hhi, *hlo;
    cudaGetSymbolAddress((void**)&xhi, gx_hi);
    cudaGetSymbolAddress((void**)&xlo, gx_lo);
    cudaGetSymbolAddress((void**)&w1h, gW1t_hi);
    cudaGetSymbolAddress((void**)&w1l, gW1t_lo);
    cudaGetSymbolAddress((void**)&w2h, gW2t_hi);
    cudaGetSymbolAddress((void**)&w2l, gW2t_lo);
    cudaGetSymbolAddress((void**)&hhi, gh_hi);
    cudaGetSymbolAddress((void**)&hlo, gh_lo);

    // 1: fused W1+W2 split + routing init
    split_wt_all_kernel<<<dim3(H_DIM / 32, H_DIM / 32, 2 * E_EXP), 256>>>(W1, W2);
    // 2: gate + x split
    gate_kernel<<<(N_TOK * 32 + 255) / 256, 256>>>(x, Wg, bg, gates_out);
    // 3: scatter
    scatter_kernel<<<(N_TOK * TOPK + 255) / 256, 256>>>();
    // 4: GEMM1  (profiled slot)
    dim3 g1(H_DIM / BN, SLOTS / BM);   // (16, 72)
    mma_gemm_kernel<D_IN, H_DIM, true, true, false>
        <<<g1, 256, SMEM_BYTES>>>(xhi, xlo, w1h, w1l, b1);
    // 5: GEMM2
    dim3 g2(D_IN / BN, SLOTS / BM);    // (4, 72)
    mma_gemm_kernel<H_DIM, D_IN, false, false, true>
        <<<g2, 256, SMEM_BYTES>>>(hhi, hlo, w2h, w2l, b2);
    // 6: combine
    combine_kernel<<<(N_TOK * (D_IN / 4) + 255) / 256, 256>>>(out);
}